// round 16
// baseline (speedup 1.0000x reference)
#include <cuda_runtime.h>

// APMLSparse: x[B,N,3], y[B,M,3] fp32 -> scalar loss. B=4, N=M=4096.
// Per row: d_j = sqrt(max(||x-y_j||^2,1e-12)), e_j=exp(-d_j), Z=sum e_j.
// Kept = d-ascending prefix while exclusive cumulative mass < 0.8*Z (incl.
// crossing entry, p>1e-10 filter). loss += sum_kept e_j*d_j / Z.
//
// R12 = R10 (350us best: 32-bin width-0.5 private banked histogram, 1/64
// sub-bins, ballot compact) + two pure deletions:
//  1) penta round + recompact deleted -- exact O(k^2) runs directly on the
//     ~35-element band list (k^2 at this size is cheaper than the penta
//     machinery's shuffles/barriers/serial section).
//  2) per-row block reduce -> per-thread rcpZ fold; one reduce per CTA.
// SIMT lesson from R11: per-lane branch-fraction "savings" don't exist;
// only unconditional deletions count.

#define NTH   512
#define NPT   8            // 4096 / NTH
#define RPC   8
#define MPTS  4096
#define NB    32           // bins per stage (width 0.5 stage 1, 1/64 stage 2)
#define HISTN (NB * NTH)   // 16384 floats = 64 KB (dynamic)
#define CAP   512
#define HIST_BYTES (HISTN * 4)

__global__ void apml_zero_out(float* o) { o[0] = 0.0f; }

__global__ __launch_bounds__(NTH, 2)
void apml_kernel(const float* __restrict__ x, const float* __restrict__ y,
                 float* __restrict__ out)
{
    extern __shared__ float hist[];     // 64 KB private histogram columns
    __shared__ float2 list[CAP];        // 4 KB boundary-band elements
    __shared__ float  binTot[NB];
    __shared__ float  warpRed[16];
    __shared__ float  s_ctl[8];         // 0:Z 1:T 2:(c1|l2f) 3:h2f 4:mLo 5:rcpZ
    __shared__ int    s_int[1];

    const int tid  = threadIdx.x, lane = tid & 31, wid = tid >> 5;
    const int cpb  = MPTS / RPC;                    // 512
    const int b    = blockIdx.x / cpb;
    const int rowBase = (blockIdx.x % cpb) * RPC;

    // 8 y-points per thread in registers, reused across RPC rows.
    float yx[NPT], yy[NPT], yz[NPT];
    const float* yb = y + (size_t)b * MPTS * 3;
#pragma unroll
    for (int k = 0; k < NPT; k++) {
        int j = k * NTH + tid;
        yx[k] = yb[j * 3 + 0];
        yy[k] = yb[j * 3 + 1];
        yz[k] = yb[j * 3 + 2];
    }

    float4* hist4 = (float4*)hist;
    float ctaAcc = 0.0f;

    for (int r = 0; r < RPC; r++) {
        const float* xp = x + ((size_t)b * MPTS + rowBase + r) * 3;
        const float x0 = __ldg(xp + 0);
        const float x1 = __ldg(xp + 1);
        const float x2 = __ldg(xp + 2);

        // ---- zero histogram (float4) ----
#pragma unroll
        for (int i = 0; i < HISTN / 4 / NTH; i++)
            hist4[tid + i * NTH] = make_float4(0.f, 0.f, 0.f, 0.f);
        if (tid == 0) s_int[0] = 0;
        __syncthreads();

        // ---- pass 1 fused with stage-1 fill: bins of width 0.5 over [0,16) ----
        float dreg[NPT];
#pragma unroll
        for (int k = 0; k < NPT; k++) {
            float dx = x0 - yx[k];
            float dy = x1 - yy[k];
            float dz = x2 - yz[k];
            float sq = fmaf(dx, dx, fmaf(dy, dy, dz * dz));
            sq = fmaxf(sq, 1e-12f);
            float d = sq * rsqrtf(sq);              // sqrt via MUFU.RSQ + FMUL
            dreg[k] = d;
            float e = __expf(-d);
            int bin = (int)(2.0f * d);              // exact 2^1 scaling
            bin = bin < (NB - 1) ? bin : (NB - 1);  // clamp stray large d
            hist[bin * NTH + tid] += e;             // conflict-free column
        }
        __syncthreads();

        // ---- stage-1 reduce: warp w sums bins 2w, 2w+1 via float4 ----
#pragma unroll
        for (int q = 0; q < 2; q++) {
            int bb = 2 * wid + q;
            float s = 0.f;
            int base = bb * (NTH / 4);
#pragma unroll
            for (int i = 0; i < NTH / 4 / 32; i++) {
                float4 v = hist4[base + lane + i * 32];
                s += (v.x + v.y) + (v.z + v.w);
            }
#pragma unroll
            for (int o = 16; o; o >>= 1) s += __shfl_xor_sync(0xffffffffu, s, o);
            if (lane == 0) binTot[bb] = s;
        }
        __syncthreads();

        // ---- stage-1 scan + pick (warp 0, 32 lanes = 32 bins) ----
        if (wid == 0) {
            float mm = binTot[lane];
            float incl = mm;
#pragma unroll
            for (int o = 1; o < 32; o <<= 1) {
                float t = __shfl_up_sync(0xffffffffu, incl, o);
                if (lane >= o) incl += t;
            }
            float total = __shfl_sync(0xffffffffu, incl, 31);
            float T = 0.8f * total;
            float excl = incl - mm;
            bool cross = (excl < T) && (incl >= T);
            unsigned bal = __ballot_sync(0xffffffffu, cross);
            int c1 = bal ? (__ffs(bal) - 1) : (NB - 1);
            float mlo = __shfl_sync(0xffffffffu, excl, c1);
            if (lane == 0) {
                s_ctl[0] = total;            // Z
                s_ctl[1] = T;
                s_ctl[2] = (float)c1;
                s_ctl[4] = mlo;              // mLo1
                s_ctl[5] = __frcp_rn(total); // rcpZ
            }
        }
        __syncthreads();
        const float Z    = s_ctl[0];
        const float T    = s_ctl[1];
        const int   c1s  = ((int)s_ctl[2]) << 5;    // c1*32
        const float mLo1 = s_ctl[4];
        const float rcpZ = s_ctl[5];

        // ---- zero histogram for stage 2 ----
#pragma unroll
        for (int i = 0; i < HISTN / 4 / NTH; i++)
            hist4[tid + i * NTH] = make_float4(0.f, 0.f, 0.f, 0.f);
        __syncthreads();

        // ---- stage-2 fill: 32 sub-bins of width 1/64 over crossing bin ----
#pragma unroll
        for (int k = 0; k < NPT; k++) {
            float d = dreg[k];
            int b2 = (int)(d * 64.0f) - c1s;        // exact: 2^ scalings nest
            if ((unsigned)b2 < (unsigned)NB) {
                float e = __expf(-d);
                hist[b2 * NTH + tid] += e;
            }
        }
        __syncthreads();

        // ---- stage-2 reduce ----
#pragma unroll
        for (int q = 0; q < 2; q++) {
            int bb = 2 * wid + q;
            float s = 0.f;
            int base = bb * (NTH / 4);
#pragma unroll
            for (int i = 0; i < NTH / 4 / 32; i++) {
                float4 v = hist4[base + lane + i * 32];
                s += (v.x + v.y) + (v.z + v.w);
            }
#pragma unroll
            for (int o = 16; o; o >>= 1) s += __shfl_xor_sync(0xffffffffu, s, o);
            if (lane == 0) binTot[bb] = s;
        }
        __syncthreads();

        // ---- stage-2 scan + pick ----
        if (wid == 0) {
            float mm = binTot[lane];
            float incl = mm;
#pragma unroll
            for (int o = 1; o < 32; o <<= 1) {
                float t = __shfl_up_sync(0xffffffffu, incl, o);
                if (lane >= o) incl += t;
            }
            float excl = incl - mm;
            bool cross = (mLo1 + excl < T) && (mLo1 + incl >= T);
            unsigned bal = __ballot_sync(0xffffffffu, cross);
            int c2 = bal ? (__ffs(bal) - 1) : (NB - 1);   // fp-mismatch fallback
            float mlo2 = mLo1 + __shfl_sync(0xffffffffu, excl, c2);
            if (lane == 0) {
                float l2f = (float)(c1s + c2) * 0.015625f;  // exact fp (/64)
                s_ctl[2] = l2f;
                s_ctl[3] = l2f + 0.015625f;
                s_ctl[4] = mlo2;
            }
        }
        __syncthreads();
        const float l2f  = s_ctl[2];
        const float h2f  = s_ctl[3];
        const float mLo2 = s_ctl[4];

        // ---- compact crossing window + accumulate surely-kept sum ----
        float acc = 0.0f;
#pragma unroll
        for (int k = 0; k < NPT; k++) {
            float d = dreg[k];
            bool kept = d < l2f;
            bool band = (!kept) && (d < h2f);
            if (kept) acc = fmaf(__expf(-d), d, acc);
            unsigned mk = __ballot_sync(0xffffffffu, band);
            if (mk) {
                int leader = __ffs(mk) - 1;
                int base2 = 0;
                if (lane == leader) base2 = atomicAdd(&s_int[0], __popc(mk));
                base2 = __shfl_sync(0xffffffffu, base2, leader);
                if (band) {
                    int idx = base2 + __popc(mk & ((1u << lane) - 1u));
                    float e = __expf(-d);
                    if (idx < CAP) list[idx] = make_float2(d, e);
                    else           acc = fmaf(e, d, acc);  // overflow fallback
                }
            }
        }
        __syncthreads();
        const int cnt = s_int[0] < CAP ? s_int[0] : CAP;

        // ---- exact O(k^2) rank resolution directly on the ~35-elem band ----
        const float Trem = T - mLo2;
        const float eThr = 1e-10f * Z;
        for (int i = tid; i < cnt; i += NTH) {
            float2 vi = list[i];
            float rm = 0.f;
            for (int j = 0; j < cnt; j++) {
                float2 vj = list[j];
                rm += ((vj.x < vi.x) || (vj.x == vi.x && j < i)) ? vj.y : 0.f;
            }
            if (rm < Trem && vi.y > eThr) acc = fmaf(vi.y, vi.x, acc);
        }

        // ---- fold row into per-thread accumulator (replaces block reduce) ----
        ctaAcc = fmaf(acc, rcpZ, ctaAcc);
        __syncthreads();   // order list/s_ctl reads before next row's rewrites
    }

    // ---- one block reduce per CTA ----
#pragma unroll
    for (int o = 16; o; o >>= 1) ctaAcc += __shfl_xor_sync(0xffffffffu, ctaAcc, o);
    if (lane == 0) warpRed[wid] = ctaAcc;
    __syncthreads();
    if (tid == 0) {
        float tot = 0.f;
#pragma unroll
        for (int i = 0; i < 16; i++) tot += warpRed[i];
        atomicAdd(out, tot);
    }
}

extern "C" void kernel_launch(void* const* d_in, const int* in_sizes, int n_in,
                              void* d_out, int out_size)
{
    const float* x = (const float*)d_in[0];
    const float* y = (const float*)d_in[1];
    float* out = (float*)d_out;

    cudaFuncSetAttribute(apml_kernel,
                         cudaFuncAttributeMaxDynamicSharedMemorySize, HIST_BYTES);

    apml_zero_out<<<1, 1>>>(out);
    const int grid = (4 * MPTS) / RPC;   // 2048 CTAs
    apml_kernel<<<grid, NTH, HIST_BYTES>>>(x, y, out);
}

// round 17
// speedup vs baseline: 1.0221x; 1.0221x over previous
#include <cuda_runtime.h>

// APMLSparse: x[B,N,3], y[B,M,3] fp32 -> scalar loss. B=4, N=M=4096.
// Per row: d_j = sqrt(max(||x-y_j||^2,1e-12)), e_j=exp(-d_j), Z=sum e_j.
// Kept = d-ascending prefix while exclusive cumulative mass < 0.8*Z (incl.
// crossing entry, p>1e-10 filter). loss += sum_kept e_j*d_j / Z.
//
// R13 = R10 core (32-bin width-0.5 private banked histogram, 1/64 sub-bins)
// with the overhead machinery stripped:
//  1) compact pass WITHOUT ballot aggregation (band ~0.85% -> direct atomic
//     append; ballot leader/shfl/popc executed in ~every warp for nothing)
//  2) read-and-clear bin reduces (both per-row zero loops deleted)
//  3) per-row block reduce -> per-thread rcpZ fold
//  4) end-of-row barrier deleted (next conflicting write is 5 barriers away)
// Barriers/row: 13 -> 7. Pass-1 / stage-2 fills, reduces, scans identical.

#define NTH   512
#define NPT   8            // 4096 / NTH
#define RPC   8
#define MPTS  4096
#define NB    32           // bins per stage (width 0.5 stage 1, 1/64 stage 2)
#define HISTN (NB * NTH)   // 16384 floats = 64 KB (dynamic)
#define CAP   512
#define HIST_BYTES (HISTN * 4)

__global__ void apml_zero_out(float* o) { o[0] = 0.0f; }

__global__ __launch_bounds__(NTH, 2)
void apml_kernel(const float* __restrict__ x, const float* __restrict__ y,
                 float* __restrict__ out)
{
    extern __shared__ float hist[];     // 64 KB private histogram columns
    __shared__ float2 list[CAP];        // 4 KB boundary-band elements
    __shared__ float  binTot[NB];
    __shared__ float  warpRed[16];
    __shared__ float  s_ctl[8];         // 0:Z 1:T 2:(c1|l2f) 3:h2f 4:mLo 5:rcpZ
    __shared__ int    s_int[1];

    const int tid  = threadIdx.x, lane = tid & 31, wid = tid >> 5;
    const int cpb  = MPTS / RPC;                    // 512
    const int b    = blockIdx.x / cpb;
    const int rowBase = (blockIdx.x % cpb) * RPC;

    // 8 y-points per thread in registers, reused across RPC rows.
    float yx[NPT], yy[NPT], yz[NPT];
    const float* yb = y + (size_t)b * MPTS * 3;
#pragma unroll
    for (int k = 0; k < NPT; k++) {
        int j = k * NTH + tid;
        yx[k] = yb[j * 3 + 0];
        yy[k] = yb[j * 3 + 1];
        yz[k] = yb[j * 3 + 2];
    }

    float4* hist4 = (float4*)hist;

    // Initial histogram zero; read-and-clear reduces keep it clean afterwards.
#pragma unroll
    for (int i = 0; i < HISTN / 4 / NTH; i++)
        hist4[tid + i * NTH] = make_float4(0.f, 0.f, 0.f, 0.f);

    float ctaAcc = 0.0f;
    __syncthreads();

    for (int r = 0; r < RPC; r++) {
        const float* xp = x + ((size_t)b * MPTS + rowBase + r) * 3;
        const float x0 = __ldg(xp + 0);
        const float x1 = __ldg(xp + 1);
        const float x2 = __ldg(xp + 2);

        // ---- pass 1 fused with stage-1 fill: bins of width 0.5 over [0,16) ----
        float dreg[NPT];
#pragma unroll
        for (int k = 0; k < NPT; k++) {
            float dx = x0 - yx[k];
            float dy = x1 - yy[k];
            float dz = x2 - yz[k];
            float sq = fmaf(dx, dx, fmaf(dy, dy, dz * dz));
            sq = fmaxf(sq, 1e-12f);
            float d = sq * rsqrtf(sq);              // sqrt via MUFU.RSQ + FMUL
            dreg[k] = d;
            float e = __expf(-d);
            int bin = (int)(2.0f * d);              // exact 2^1 scaling
            bin = bin < (NB - 1) ? bin : (NB - 1);  // clamp stray large d
            hist[bin * NTH + tid] += e;             // conflict-free column
        }
        __syncthreads();

        // ---- stage-1 reduce: warp w sums bins 2w, 2w+1 (and clears them) ----
#pragma unroll
        for (int q = 0; q < 2; q++) {
            int bb = 2 * wid + q;
            float s = 0.f;
            int base = bb * (NTH / 4);
#pragma unroll
            for (int i = 0; i < NTH / 4 / 32; i++) {
                float4 v = hist4[base + lane + i * 32];
                s += (v.x + v.y) + (v.z + v.w);
                hist4[base + lane + i * 32] = make_float4(0.f, 0.f, 0.f, 0.f);
            }
#pragma unroll
            for (int o = 16; o; o >>= 1) s += __shfl_xor_sync(0xffffffffu, s, o);
            if (lane == 0) binTot[bb] = s;
        }
        __syncthreads();

        // ---- stage-1 scan + pick (warp 0, 32 lanes = 32 bins) ----
        if (wid == 0) {
            float mm = binTot[lane];
            float incl = mm;
#pragma unroll
            for (int o = 1; o < 32; o <<= 1) {
                float t = __shfl_up_sync(0xffffffffu, incl, o);
                if (lane >= o) incl += t;
            }
            float total = __shfl_sync(0xffffffffu, incl, 31);
            float T = 0.8f * total;
            float excl = incl - mm;
            bool cross = (excl < T) && (incl >= T);
            unsigned bal = __ballot_sync(0xffffffffu, cross);
            int c1 = bal ? (__ffs(bal) - 1) : (NB - 1);
            float mlo = __shfl_sync(0xffffffffu, excl, c1);
            if (lane == 0) {
                s_ctl[0] = total;            // Z
                s_ctl[1] = T;
                s_ctl[2] = (float)c1;
                s_ctl[4] = mlo;              // mLo1
                s_ctl[5] = __frcp_rn(total); // rcpZ
                s_int[0] = 0;   // prior-row readers hold cnt in registers
            }
        }
        __syncthreads();
        const float Z    = s_ctl[0];
        const float T    = s_ctl[1];
        const int   c1s  = ((int)s_ctl[2]) << 5;    // c1*32
        const float mLo1 = s_ctl[4];
        const float rcpZ = s_ctl[5];

        // ---- stage-2 fill: 32 sub-bins of width 1/64 over crossing bin ----
#pragma unroll
        for (int k = 0; k < NPT; k++) {
            float d = dreg[k];
            int b2 = (int)(d * 64.0f) - c1s;        // exact: 2^ scalings nest
            if ((unsigned)b2 < (unsigned)NB) {
                float e = __expf(-d);
                hist[b2 * NTH + tid] += e;
            }
        }
        __syncthreads();

        // ---- stage-2 reduce (and clear) ----
#pragma unroll
        for (int q = 0; q < 2; q++) {
            int bb = 2 * wid + q;
            float s = 0.f;
            int base = bb * (NTH / 4);
#pragma unroll
            for (int i = 0; i < NTH / 4 / 32; i++) {
                float4 v = hist4[base + lane + i * 32];
                s += (v.x + v.y) + (v.z + v.w);
                hist4[base + lane + i * 32] = make_float4(0.f, 0.f, 0.f, 0.f);
            }
#pragma unroll
            for (int o = 16; o; o >>= 1) s += __shfl_xor_sync(0xffffffffu, s, o);
            if (lane == 0) binTot[bb] = s;
        }
        __syncthreads();

        // ---- stage-2 scan + pick ----
        if (wid == 0) {
            float mm = binTot[lane];
            float incl = mm;
#pragma unroll
            for (int o = 1; o < 32; o <<= 1) {
                float t = __shfl_up_sync(0xffffffffu, incl, o);
                if (lane >= o) incl += t;
            }
            float excl = incl - mm;
            bool cross = (mLo1 + excl < T) && (mLo1 + incl >= T);
            unsigned bal = __ballot_sync(0xffffffffu, cross);
            int c2 = bal ? (__ffs(bal) - 1) : (NB - 1);   // fp-mismatch fallback
            float mlo2 = mLo1 + __shfl_sync(0xffffffffu, excl, c2);
            if (lane == 0) {
                float l2f = (float)(c1s + c2) * 0.015625f;  // exact fp (/64)
                s_ctl[2] = l2f;
                s_ctl[3] = l2f + 0.015625f;
                s_ctl[4] = mlo2;
            }
        }
        __syncthreads();
        const float l2f  = s_ctl[2];
        const float h2f  = s_ctl[3];
        const float mLo2 = s_ctl[4];

        // ---- compact (no ballot): kept FMA; band (~0.85%) direct append ----
        float acc = 0.0f;
#pragma unroll
        for (int k = 0; k < NPT; k++) {
            float d = dreg[k];
            if (d < h2f) {                          // ~73% of lanes
                float e = __expf(-d);
                if (d < l2f) {
                    acc = fmaf(e, d, acc);
                } else {                            // band: rare
                    int idx = atomicAdd(&s_int[0], 1);
                    if (idx < CAP) list[idx] = make_float2(d, e);
                    else           acc = fmaf(e, d, acc);  // overflow fallback
                }
            }
        }
        __syncthreads();
        const int cnt = s_int[0] < CAP ? s_int[0] : CAP;

        // ---- exact O(k^2) rank resolution on the ~35-elem band ----
        const float Trem = T - mLo2;
        const float eThr = 1e-10f * Z;
        for (int i = tid; i < cnt; i += NTH) {
            float2 vi = list[i];
            float rm = 0.f;
            for (int j = 0; j < cnt; j++) {
                float2 vj = list[j];
                rm += ((vj.x < vi.x) || (vj.x == vi.x && j < i)) ? vj.y : 0.f;
            }
            if (rm < Trem && vi.y > eThr) acc = fmaf(vi.y, vi.x, acc);
        }

        // ---- fold row into per-thread accumulator; no end-of-row barrier:
        //      next conflicting smem write (list, next compact) is 5 barriers
        //      downstream; s_int reset rides in next scan-1.
        ctaAcc = fmaf(acc, rcpZ, ctaAcc);
    }

    // ---- one block reduce per CTA ----
#pragma unroll
    for (int o = 16; o; o >>= 1) ctaAcc += __shfl_xor_sync(0xffffffffu, ctaAcc, o);
    if (lane == 0) warpRed[wid] = ctaAcc;
    __syncthreads();
    if (tid == 0) {
        float tot = 0.f;
#pragma unroll
        for (int i = 0; i < 16; i++) tot += warpRed[i];
        atomicAdd(out, tot);
    }
}

extern "C" void kernel_launch(void* const* d_in, const int* in_sizes, int n_in,
                              void* d_out, int out_size)
{
    const float* x = (const float*)d_in[0];
    const float* y = (const float*)d_in[1];
    float* out = (float*)d_out;

    cudaFuncSetAttribute(apml_kernel,
                         cudaFuncAttributeMaxDynamicSharedMemorySize, HIST_BYTES);

    apml_zero_out<<<1, 1>>>(out);
    const int grid = (4 * MPTS) / RPC;   // 2048 CTAs
    apml_kernel<<<grid, NTH, HIST_BYTES>>>(x, y, out);
}